// round 1
// baseline (speedup 1.0000x reference)
#include <cuda_runtime.h>
#include <stdint.h>

#define HH 1024
#define WW 2048
#define HW (HH * WW)              // 2,097,152
#define NCLS 34
#define NI 128
#define NB 10                     // "thing" classes 24..33
#define NBINS (NI * NB)           // 1280

// Scratch (no cudaMalloc allowed): per-(instance, thing-class) statistics.
__device__ int   g_counts[NBINS];
__device__ float g_sums[NBINS];

// ---------------------------------------------------------------------------
// Kernel 1: zero the global stat bins (must be re-zeroed every launch for
// graph-replay determinism).
// ---------------------------------------------------------------------------
__global__ void zero_stats_kernel() {
    int t = blockIdx.x * blockDim.x + threadIdx.x;
    if (t < NBINS) { g_counts[t] = 0; g_sums[t] = 0.0f; }
}

// ---------------------------------------------------------------------------
// Kernel 2: zero-fill the inst_masks region of d_out (128*HW floats = 1.07 GB).
// Pure float4 stores — keep it ALU-free so it rides the DRAM write roofline.
// Launch exactly 128*HW/4 = 67,108,864 threads (262144 blocks x 256).
// ---------------------------------------------------------------------------
__global__ void zero_masks_kernel(float4* __restrict__ out4) {
    size_t i = (size_t)blockIdx.x * blockDim.x + threadIdx.x;
    out4[i] = make_float4(0.f, 0.f, 0.f, 0.f);
}

// ---------------------------------------------------------------------------
// Kernel 3: single pass over pixels.
//   - compute inst = (24 <= seg <= 33) ? instance_maps : 0
//   - scatter 1.0f into out[(inst-1)*HW + p]     (sparse, ~617K stores)
//   - shared-mem histogram of counts[(inst-1)][seg-24]
//   - shared-mem accumulation of sums[(inst-1)][c] for channels 24..33
// Each thread owns 4 consecutive pixels (int4 / float4 loads).
// Grid: 2048 blocks x 256 threads = 524288 threads * 4 px = HW exactly.
// ---------------------------------------------------------------------------
__global__ void stats_scatter_kernel(const int4*   __restrict__ seg4,
                                     const int4*   __restrict__ inst4,
                                     const float4* __restrict__ probs4,
                                     float*        __restrict__ out_masks) {
    __shared__ int   s_cnt[NBINS];
    __shared__ float s_sum[NBINS];

    const int tid = threadIdx.x;
    for (int i = tid; i < NBINS; i += blockDim.x) { s_cnt[i] = 0; s_sum[i] = 0.0f; }
    __syncthreads();

    const int t  = blockIdx.x * blockDim.x + tid;   // 4-pixel group index
    const int p0 = t * 4;

    const int4 sg = seg4[t];
    const int4 im = inst4[t];
    int ss[4] = { sg.x, sg.y, sg.z, sg.w };
    int iv[4] = { im.x, im.y, im.z, im.w };
    int ii[4];

    #pragma unroll
    for (int j = 0; j < 4; ++j) {
        const int s = ss[j];
        const int inst = (s >= 24 && s <= 33) ? iv[j] : 0;
        ii[j] = inst;
        if (inst > 0) {
            out_masks[(size_t)(inst - 1) * HW + p0 + j] = 1.0f;
            atomicAdd(&s_cnt[(inst - 1) * NB + (s - 24)], 1);
        }
    }

    // Only load the 10 probability channels if one of our 4 pixels needs them.
    if (ii[0] | ii[1] | ii[2] | ii[3]) {
        #pragma unroll
        for (int c = 0; c < NB; ++c) {
            const float4 pv = probs4[(size_t)(24 + c) * (HW / 4) + t];
            const float pa[4] = { pv.x, pv.y, pv.z, pv.w };
            #pragma unroll
            for (int j = 0; j < 4; ++j)
                if (ii[j] > 0)
                    atomicAdd(&s_sum[(ii[j] - 1) * NB + c], pa[j]);
        }
    }

    __syncthreads();
    // Flush block-local histograms. Skips zero bins; atomicAdd-no-return -> RED.
    for (int i = tid; i < NBINS; i += blockDim.x) {
        const int   cv = s_cnt[i];
        const float sv = s_sum[i];
        if (cv)          atomicAdd(&g_counts[i], cv);
        if (sv != 0.0f)  atomicAdd(&g_sums[i], sv);
    }
}

// ---------------------------------------------------------------------------
// Kernel 4: per-instance finalize. argmax over the 10 thing-class bins
// (classes 0..23 have zero counts, so if total>0 the global argmax is
// 24+best_bin with first-occurrence tie semantics; if total==0 argmax is 0
// and seg_prob = 0 / max(0,1) = 0).
// Tail layout (float32), after the 128*HW mask region, matching the
// reference tuple order: inst_class, instance_probs, seg_prob, total, valid.
// ---------------------------------------------------------------------------
__global__ void finalize_kernel(const float* __restrict__ inst_probs,
                                float*       __restrict__ out) {
    const int i = threadIdx.x;                      // 0..127
    int tot = 0, best = 0, bestc = 0;
    #pragma unroll
    for (int c = 0; c < NB; ++c) {
        const int v = g_counts[i * NB + c];
        tot += v;
        if (v > best) { best = v; bestc = c; }      // strict > == first occurrence
    }
    float cls = 0.0f, segp = 0.0f;
    if (tot > 0) {
        cls  = (float)(24 + bestc);
        segp = g_sums[i * NB + bestc] / (float)tot;
    }
    float* tail = out + (size_t)NI * HW;
    tail[0 * NI + i] = cls;
    tail[1 * NI + i] = inst_probs[i];
    tail[2 * NI + i] = segp;
    tail[3 * NI + i] = (float)tot;
    tail[4 * NI + i] = (tot > 0) ? 1.0f : 0.0f;
}

// ---------------------------------------------------------------------------
extern "C" void kernel_launch(void* const* d_in, const int* in_sizes, int n_in,
                              void* d_out, int out_size) {
    const int*   seg    = (const int*)  d_in[0];   // (H, W) int32
    const int*   inst   = (const int*)  d_in[1];   // (H, W) int32
    const float* probs  = (const float*)d_in[2];   // (C, H, W) float32
    const float* iprobs = (const float*)d_in[3];   // (128,) float32
    float* out = (float*)d_out;

    zero_stats_kernel<<<(NBINS + 255) / 256, 256>>>();
    zero_masks_kernel<<<(NI * (HW / 4)) / 256, 256>>>((float4*)out);
    stats_scatter_kernel<<<(HW / 4) / 256, 256>>>(
        (const int4*)seg, (const int4*)inst, (const float4*)probs, out);
    finalize_kernel<<<1, NI>>>(iprobs, out);
}